// round 14
// baseline (speedup 1.0000x reference)
#include <cuda_runtime.h>
#include <cuda_fp16.h>
#include <cuda_bf16.h>
#include <cstdint>

// ---------------- problem constants ----------------
#define GN 100000          // nodes
#define GD 256             // d_in = d_out
#define GK 512             // 2*d_in
#define MAXDEG 16

#define TILE_M 64
#define NMT ((GN + TILE_M - 1) / TILE_M)     // 1563 m-tiles
#define NCTAS_G (NMT * 2)                    // x2 n-halves = 3126 CTAs

// ---------------- scratch (device globals; no allocs allowed) ----------------
__device__ __align__(256) __half g_xh[(GN + 1) * GD];   // x in fp16, + zero row at index GN
__device__ __align__(256) __half g_aggh[GN * GD];       // neighbor mean, fp16
__device__ __align__(256) __half g_wh[GK * GD];         // W in fp16, [n][k] row-major
__device__ int g_is64;                                  // edge_index dtype flag

// ---------------- small helpers ----------------
__device__ __forceinline__ uint32_t smem_u32(const void* p) {
    uint32_t a;
    asm("{ .reg .u64 t; cvta.to.shared.u64 t, %1; cvt.u32.u64 %0, t; }" : "=r"(a) : "l"(p));
    return a;
}

__device__ __forceinline__ void cp_async16(uint32_t dst, const void* src, int pred) {
    int sz = pred ? 16 : 0;
    asm volatile("cp.async.cg.shared.global [%0], [%1], 16, %2;"
                 :: "r"(dst), "l"(src), "r"(sz) : "memory");
}
__device__ __forceinline__ void cp_async_commit() {
    asm volatile("cp.async.commit_group;" ::: "memory");
}
__device__ __forceinline__ void cp_async_wait0() {
    asm volatile("cp.async.wait_group 0;" ::: "memory");
}

__device__ __forceinline__ void ldsm_x4(uint32_t& r0, uint32_t& r1, uint32_t& r2, uint32_t& r3,
                                        uint32_t addr) {
    asm volatile("ldmatrix.sync.aligned.m8n8.x4.shared.b16 {%0,%1,%2,%3}, [%4];"
                 : "=r"(r0), "=r"(r1), "=r"(r2), "=r"(r3) : "r"(addr));
}

__device__ __forceinline__ void mma16816(float& c0, float& c1, float& c2, float& c3,
                                         uint32_t a0, uint32_t a1, uint32_t a2, uint32_t a3,
                                         uint32_t b0, uint32_t b1) {
    asm volatile(
        "mma.sync.aligned.m16n8k16.row.col.f32.f16.f16.f32 "
        "{%0,%1,%2,%3}, {%4,%5,%6,%7}, {%8,%9}, {%0,%1,%2,%3};"
        : "+f"(c0), "+f"(c1), "+f"(c2), "+f"(c3)
        : "r"(a0), "r"(a1), "r"(a2), "r"(a3), "r"(b0), "r"(b1));
}

// streaming store (evict-first): minimizes L2 pollution of the shared x set
__device__ __forceinline__ void stcs_f2(float* p, float2 v) {
    asm volatile("st.global.cs.v2.f32 [%0], {%1,%2};"
                 :: "l"(p), "f"(v.x), "f"(v.y) : "memory");
}

// ---------------- kernel 1: x -> fp16 (+ zero pad row) ----------------
__global__ void cvt_x_kernel(const float* __restrict__ x) {
    size_t i = ((size_t)blockIdx.x * blockDim.x + threadIdx.x) * 8;
    const size_t total = (size_t)(GN + 1) * GD;
    if (i >= total) return;
    uint4 o;
    if (i < (size_t)GN * GD) {
        float4 a = *(const float4*)(x + i);
        float4 b = *(const float4*)(x + i + 4);
        __half2 h0 = __floats2half2_rn(a.x, a.y);
        __half2 h1 = __floats2half2_rn(a.z, a.w);
        __half2 h2 = __floats2half2_rn(b.x, b.y);
        __half2 h3 = __floats2half2_rn(b.z, b.w);
        o.x = *reinterpret_cast<unsigned*>(&h0);
        o.y = *reinterpret_cast<unsigned*>(&h1);
        o.z = *reinterpret_cast<unsigned*>(&h2);
        o.w = *reinterpret_cast<unsigned*>(&h3);
    } else {
        o = make_uint4(0, 0, 0, 0);
    }
    *(uint4*)(g_xh + i) = o;
}

// ---------------- kernel 1w: W -> fp16 ----------------
__global__ void cvt_w_kernel(const float* __restrict__ W) {
    size_t i = ((size_t)blockIdx.x * blockDim.x + threadIdx.x) * 8;
    if (i >= (size_t)GD * GK) return;
    float4 a = *(const float4*)(W + i);
    float4 b = *(const float4*)(W + i + 4);
    __half2 h0 = __floats2half2_rn(a.x, a.y);
    __half2 h1 = __floats2half2_rn(a.z, a.w);
    __half2 h2 = __floats2half2_rn(b.x, b.y);
    __half2 h3 = __floats2half2_rn(b.z, b.w);
    uint4 o;
    o.x = *reinterpret_cast<unsigned*>(&h0);
    o.y = *reinterpret_cast<unsigned*>(&h1);
    o.z = *reinterpret_cast<unsigned*>(&h2);
    o.w = *reinterpret_cast<unsigned*>(&h3);
    *(uint4*)(g_wh + i) = o;
}

// ---------------- kernel 1b: detect edge dtype (int32 vs int64) ----------------
__global__ void detect_kernel(const int* __restrict__ e) {
    int v = e[2 * threadIdx.x + 1];           // odd 32-bit words of first rows
    int bad = (v != 0 && v != -1) ? 1 : 0;    // int64 => these are all 0 / -1
    int any = __syncthreads_or(bad);
    if (threadIdx.x == 0) g_is64 = any ? 0 : 1;
}

// ---------------- kernel 2: mean aggregation (one warp per node, monolithic) --------
__global__ void agg_kernel(const int* __restrict__ edges) {
    int node = (int)((blockIdx.x * blockDim.x + threadIdx.x) >> 5);
    int lane = threadIdx.x & 31;
    if (node >= GN) return;
    int is64 = g_is64;
    int e = -1;
    if (lane < MAXDEG) {
        if (is64) {
            long long t = ((const long long*)edges)[(size_t)node * MAXDEG + lane];
            e = (int)t;
        } else {
            e = edges[node * MAXDEG + lane];
        }
    }
    unsigned bal = __ballot_sync(0xffffffffu, e >= 0);
    float inv = 1.0f / (float)__popc(bal & 0xffffu);

    float acc[8];
#pragma unroll
    for (int q = 0; q < 8; q++) acc[q] = 0.0f;

#pragma unroll
    for (int q4 = 0; q4 < 4; q4++) {
        uint4 v[4];
#pragma unroll
        for (int d = 0; d < 4; d++) {
            int ej = __shfl_sync(0xffffffffu, e, q4 * 4 + d);
            unsigned row = (ej >= 0) ? (unsigned)ej : (unsigned)GN;   // pad -> zero row
            v[d] = *(const uint4*)(g_xh + (size_t)row * GD + lane * 8);
        }
        const __half2* p0 = (const __half2*)&v[0];
        const __half2* p1 = (const __half2*)&v[1];
        const __half2* p2 = (const __half2*)&v[2];
        const __half2* p3 = (const __half2*)&v[3];
#pragma unroll
        for (int j = 0; j < 4; j++) {
            __half2 s01 = __hadd2(p0[j], p1[j]);
            __half2 s23 = __hadd2(p2[j], p3[j]);
            __half2 s = __hadd2(s01, s23);
            float2 f = __half22float2(s);
            acc[j * 2] += f.x;
            acc[j * 2 + 1] += f.y;
        }
    }
    __half2 r0 = __floats2half2_rn(acc[0] * inv, acc[1] * inv);
    __half2 r1 = __floats2half2_rn(acc[2] * inv, acc[3] * inv);
    __half2 r2 = __floats2half2_rn(acc[4] * inv, acc[5] * inv);
    __half2 r3 = __floats2half2_rn(acc[6] * inv, acc[7] * inv);
    uint4 o;
    o.x = *reinterpret_cast<unsigned*>(&r0);
    o.y = *reinterpret_cast<unsigned*>(&r1);
    o.z = *reinterpret_cast<unsigned*>(&r2);
    o.w = *reinterpret_cast<unsigned*>(&r3);
    *(uint4*)(g_aggh + (size_t)node * GD + lane * 8) = o;
}

// ---------------- kernel 3: K-split mma.sync GEMM halves -----------------------------
// PHASE 0: out  = x   @ Wx^T            (A = g_xh,  W cols [0,256),  streaming store)
// PHASE 1: out += agg @ Wa^T + bias     (A = g_aggh, W cols [256,512), rmw store)
// CTA tile 64(M) x 128(N), 256 thr (8 warps), 3 CTAs/SM, warp tile 32x32, K chunks of 64.

#define KC 64
#define NCHH 4          // chunks per half

// SMEM: A dbuf 2 x 8KB @ 0 ; B dbuf 2 x 16KB @ 16384. 16B-seg XOR swizzle. Total 48KB.
#define SA(buf) ((buf) * 8192)
#define SB(buf) (16384 + (buf) * 16384)
#define SMEM_DYN 49152

template <int PHASE>
__global__ void __launch_bounds__(256, 3)
gemm_half_kernel(const float* __restrict__ bias, float* __restrict__ out) {
    extern __shared__ char smem_raw[];
    uint32_t sb = smem_u32(smem_raw);
    const int tid = threadIdx.x;
    const int wid = tid >> 5, lane = tid & 31;
    const int wm = wid & 1;              // 0..1 -> 32 rows
    const int wn = wid >> 1;             // 0..3 -> 32 cols
    const int m0 = (blockIdx.x >> 1) * TILE_M;
    const int n0 = (blockIdx.x & 1) << 7;     // 0 or 128

    auto issue_chunk = [&](int c, int buf) {
        const __half* asrc = PHASE ? g_aggh : g_xh;
#pragma unroll
        for (int i = 0; i < 2; i++) {
            int s = tid + i * 256;
            int row = s >> 3, seg = s & 7;
            int m = m0 + row;
            uint32_t dst = sb + SA(buf) + row * 128 + ((seg ^ (row & 7)) << 4);
            cp_async16(dst, asrc + (size_t)m * GD + c * KC + seg * 8, m < GN);
        }
#pragma unroll
        for (int i = 0; i < 4; i++) {
            int s = tid + i * 256;
            int n = s >> 3, seg = s & 7;
            uint32_t dst = sb + SB(buf) + n * 128 + ((seg ^ (n & 7)) << 4);
            cp_async16(dst, g_wh + (size_t)(n0 + n) * GK + PHASE * 256 + c * KC + seg * 8, 1);
        }
        cp_async_commit();
    };

    float acc[2][4][4];
#pragma unroll
    for (int mt = 0; mt < 2; mt++)
#pragma unroll
        for (int nt = 0; nt < 4; nt++)
#pragma unroll
            for (int q = 0; q < 4; q++) acc[mt][nt][q] = 0.0f;

    issue_chunk(0, 0);

    const int lrow = lane & 15;          // row within 16-row tile
    const int lcg = lane >> 4;           // 16B column group (0/1)

#pragma unroll 1
    for (int c = 0; c < NCHH; c++) {
        cp_async_wait0();
        __syncthreads();
        if (c + 1 < NCHH) issue_chunk(c + 1, (c + 1) & 1);

        uint32_t abase = sb + SA(c & 1);
        uint32_t bbase = sb + SB(c & 1);
#pragma unroll
        for (int ks = 0; ks < 4; ks++) {
            uint32_t a0[2], a1[2], a2[2], a3[2];
            uint32_t b0[2], b1[2], b2[2], b3[2];
#pragma unroll
            for (int mt = 0; mt < 2; mt++) {
                int row = wm * 32 + mt * 16 + lrow;
                uint32_t addr = abase + row * 128 + (((ks * 2 + lcg) ^ (row & 7)) << 4);
                ldsm_x4(a0[mt], a1[mt], a2[mt], a3[mt], addr);
            }
#pragma unroll
            for (int np = 0; np < 2; np++) {     // 2 n-tile pairs (16 n-rows each)
                int row = wn * 32 + np * 16 + lrow;
                uint32_t addr = bbase + row * 128 + (((ks * 2 + lcg) ^ (row & 7)) << 4);
                ldsm_x4(b0[np], b1[np], b2[np], b3[np], addr);
            }
#pragma unroll
            for (int mt = 0; mt < 2; mt++) {
#pragma unroll
                for (int np = 0; np < 2; np++) {
                    mma16816(acc[mt][np * 2][0], acc[mt][np * 2][1],
                             acc[mt][np * 2][2], acc[mt][np * 2][3],
                             a0[mt], a1[mt], a2[mt], a3[mt], b0[np], b2[np]);
                    mma16816(acc[mt][np * 2 + 1][0], acc[mt][np * 2 + 1][1],
                             acc[mt][np * 2 + 1][2], acc[mt][np * 2 + 1][3],
                             a0[mt], a1[mt], a2[mt], a3[mt], b1[np], b3[np]);
                }
            }
        }
        __syncthreads();
    }

    // ---- epilogue ----
    const int qm = lane >> 2;            // 0..7 row within 8
    const int qn = (lane & 3) * 2;       // col pair
    float2 bb[4];
    if (PHASE) {
#pragma unroll
        for (int nt = 0; nt < 4; nt++) {
            int ncol = n0 + wn * 32 + nt * 8 + qn;
            bb[nt] = *(const float2*)(bias + ncol);
        }
    }
#pragma unroll
    for (int mt = 0; mt < 2; mt++) {
        int r0 = m0 + wm * 32 + mt * 16 + qm;
        int r1 = r0 + 8;
#pragma unroll
        for (int nt = 0; nt < 4; nt++) {
            int ncol = n0 + wn * 32 + nt * 8 + qn;
            if (r0 < GN) {
                float* p = out + (size_t)r0 * GD + ncol;
                if (PHASE) {
                    float2 prev = *(float2*)p;
                    *(float2*)p = make_float2(prev.x + acc[mt][nt][0] + bb[nt].x,
                                              prev.y + acc[mt][nt][1] + bb[nt].y);
                } else {
                    stcs_f2(p, make_float2(acc[mt][nt][0], acc[mt][nt][1]));
                }
            }
            if (r1 < GN) {
                float* p = out + (size_t)r1 * GD + ncol;
                if (PHASE) {
                    float2 prev = *(float2*)p;
                    *(float2*)p = make_float2(prev.x + acc[mt][nt][2] + bb[nt].x,
                                              prev.y + acc[mt][nt][3] + bb[nt].y);
                } else {
                    stcs_f2(p, make_float2(acc[mt][nt][2], acc[mt][nt][3]));
                }
            }
        }
    }
}

// ---------------- launch: K-split GEMM; x-half overlaps agg ----------------
extern "C" void kernel_launch(void* const* d_in, const int* in_sizes, int n_in,
                              void* d_out, int out_size) {
    const float* x  = (const float*)d_in[0];
    const int*   ei = (const int*)d_in[1];
    const float* W  = (const float*)d_in[2];
    const float* b  = (const float*)d_in[3];
    float* out = (float*)d_out;
    (void)in_sizes; (void)n_in; (void)out_size;

    static int init_done = 0;
    static int overlap_ok = 1;
    static cudaStream_t s1;
    static cudaEvent_t e0, e1, e2, e3;
    if (!init_done) {
        init_done = 1;
        cudaFuncSetAttribute(gemm_half_kernel<0>, cudaFuncAttributeMaxDynamicSharedMemorySize, SMEM_DYN);
        cudaFuncSetAttribute(gemm_half_kernel<1>, cudaFuncAttributeMaxDynamicSharedMemorySize, SMEM_DYN);
        if (cudaStreamCreateWithFlags(&s1, cudaStreamNonBlocking) != cudaSuccess) overlap_ok = 0;
        if (cudaEventCreateWithFlags(&e0, cudaEventDisableTiming) != cudaSuccess) overlap_ok = 0;
        if (cudaEventCreateWithFlags(&e1, cudaEventDisableTiming) != cudaSuccess) overlap_ok = 0;
        if (cudaEventCreateWithFlags(&e2, cudaEventDisableTiming) != cudaSuccess) overlap_ok = 0;
        if (cudaEventCreateWithFlags(&e3, cudaEventDisableTiming) != cudaSuccess) overlap_ok = 0;
    }

    int cvt_threads = ((GN + 1) * GD) / 8;

    if (overlap_ok) {
        // fork s1 from capture origin; tiny prep concurrent with big x cvt
        cudaEventRecord(e0, 0);
        cudaStreamWaitEvent(s1, e0, 0);
        cvt_w_kernel<<<(GD * GK / 8 + 255) / 256, 256, 0, s1>>>(W);
        detect_kernel<<<1, 256, 0, s1>>>(ei);
        cudaEventRecord(e1, s1);
        cvt_x_kernel<<<(cvt_threads + 255) / 256, 256>>>(x);
        cudaStreamWaitEvent(0, e1, 0);        // main: g_is64 + g_wh ready
        cudaEventRecord(e2, 0);               // x + W + is64 all complete here
        cudaStreamWaitEvent(s1, e2, 0);
        // s1: x-half GEMM (streams x, .cs out stores) || main: agg (random x gathers)
        gemm_half_kernel<0><<<NCTAS_G, 256, SMEM_DYN, s1>>>(b, out);
        cudaEventRecord(e3, s1);
        agg_kernel<<<(GN + 7) / 8, 256>>>(ei);
        cudaStreamWaitEvent(0, e3, 0);        // join before rmw of out
        gemm_half_kernel<1><<<NCTAS_G, 256, SMEM_DYN>>>(b, out);
    } else {
        cvt_x_kernel<<<(cvt_threads + 255) / 256, 256>>>(x);
        cvt_w_kernel<<<(GD * GK / 8 + 255) / 256, 256>>>(W);
        detect_kernel<<<1, 256>>>(ei);
        agg_kernel<<<(GN + 7) / 8, 256>>>(ei);
        gemm_half_kernel<0><<<NCTAS_G, 256, SMEM_DYN>>>(b, out);
        gemm_half_kernel<1><<<NCTAS_G, 256, SMEM_DYN>>>(b, out);
    }
}

// round 15
// speedup vs baseline: 1.2025x; 1.2025x over previous
#include <cuda_runtime.h>
#include <cuda_fp16.h>
#include <cuda_bf16.h>
#include <cstdint>

// ---------------- problem constants ----------------
#define GN 100000          // nodes
#define GD 256             // d_in = d_out
#define GK 512             // 2*d_in
#define MAXDEG 16

#define TILE_M 128
#define NMT ((GN + TILE_M - 1) / TILE_M)     // 782 m-tiles
#define NCTAS_G (NMT * 2)                    // x2 n-halves = 1564 CTAs

// ---------------- scratch (device globals; no allocs allowed) ----------------
__device__ __align__(256) __half g_xh[(GN + 1) * GD];   // x in fp16, + zero row at index GN
__device__ __align__(256) __half g_aggh[GN * GD];       // neighbor mean, fp16
__device__ __align__(256) __half g_wh[GK * GD];         // W in fp16, [n][k] row-major
__device__ int g_is64;                                  // edge_index dtype flag

// ---------------- small helpers ----------------
__device__ __forceinline__ uint32_t smem_u32(const void* p) {
    uint32_t a;
    asm("{ .reg .u64 t; cvta.to.shared.u64 t, %1; cvt.u32.u64 %0, t; }" : "=r"(a) : "l"(p));
    return a;
}

__device__ __forceinline__ void cp_async16(uint32_t dst, const void* src, int pred) {
    int sz = pred ? 16 : 0;
    asm volatile("cp.async.cg.shared.global [%0], [%1], 16, %2;"
                 :: "r"(dst), "l"(src), "r"(sz) : "memory");
}
__device__ __forceinline__ void cp_async_commit() {
    asm volatile("cp.async.commit_group;" ::: "memory");
}
__device__ __forceinline__ void cp_async_wait0() {
    asm volatile("cp.async.wait_group 0;" ::: "memory");
}

__device__ __forceinline__ void ldsm_x4(uint32_t& r0, uint32_t& r1, uint32_t& r2, uint32_t& r3,
                                        uint32_t addr) {
    asm volatile("ldmatrix.sync.aligned.m8n8.x4.shared.b16 {%0,%1,%2,%3}, [%4];"
                 : "=r"(r0), "=r"(r1), "=r"(r2), "=r"(r3) : "r"(addr));
}

__device__ __forceinline__ void mma16816(float& c0, float& c1, float& c2, float& c3,
                                         uint32_t a0, uint32_t a1, uint32_t a2, uint32_t a3,
                                         uint32_t b0, uint32_t b1) {
    asm volatile(
        "mma.sync.aligned.m16n8k16.row.col.f32.f16.f16.f32 "
        "{%0,%1,%2,%3}, {%4,%5,%6,%7}, {%8,%9}, {%0,%1,%2,%3};"
        : "+f"(c0), "+f"(c1), "+f"(c2), "+f"(c3)
        : "r"(a0), "r"(a1), "r"(a2), "r"(a3), "r"(b0), "r"(b1));
}

// ---------------- kernel 1: x -> fp16 (+ zero pad row) ----------------
__global__ void cvt_x_kernel(const float* __restrict__ x) {
    size_t i = ((size_t)blockIdx.x * blockDim.x + threadIdx.x) * 8;
    const size_t total = (size_t)(GN + 1) * GD;
    if (i >= total) return;
    uint4 o;
    if (i < (size_t)GN * GD) {
        float4 a = *(const float4*)(x + i);
        float4 b = *(const float4*)(x + i + 4);
        __half2 h0 = __floats2half2_rn(a.x, a.y);
        __half2 h1 = __floats2half2_rn(a.z, a.w);
        __half2 h2 = __floats2half2_rn(b.x, b.y);
        __half2 h3 = __floats2half2_rn(b.z, b.w);
        o.x = *reinterpret_cast<unsigned*>(&h0);
        o.y = *reinterpret_cast<unsigned*>(&h1);
        o.z = *reinterpret_cast<unsigned*>(&h2);
        o.w = *reinterpret_cast<unsigned*>(&h3);
    } else {
        o = make_uint4(0, 0, 0, 0);
    }
    *(uint4*)(g_xh + i) = o;
}

// ---------------- kernel 1w: W -> fp16 ----------------
__global__ void cvt_w_kernel(const float* __restrict__ W) {
    size_t i = ((size_t)blockIdx.x * blockDim.x + threadIdx.x) * 8;
    if (i >= (size_t)GD * GK) return;
    float4 a = *(const float4*)(W + i);
    float4 b = *(const float4*)(W + i + 4);
    __half2 h0 = __floats2half2_rn(a.x, a.y);
    __half2 h1 = __floats2half2_rn(a.z, a.w);
    __half2 h2 = __floats2half2_rn(b.x, b.y);
    __half2 h3 = __floats2half2_rn(b.z, b.w);
    uint4 o;
    o.x = *reinterpret_cast<unsigned*>(&h0);
    o.y = *reinterpret_cast<unsigned*>(&h1);
    o.z = *reinterpret_cast<unsigned*>(&h2);
    o.w = *reinterpret_cast<unsigned*>(&h3);
    *(uint4*)(g_wh + i) = o;
}

// ---------------- kernel 1b: detect edge dtype (int32 vs int64) ----------------
__global__ void detect_kernel(const int* __restrict__ e) {
    int v = e[2 * threadIdx.x + 1];           // odd 32-bit words of first rows
    int bad = (v != 0 && v != -1) ? 1 : 0;    // int64 => these are all 0 / -1
    int any = __syncthreads_or(bad);
    if (threadIdx.x == 0) g_is64 = any ? 0 : 1;
}

// ---------------- kernel 2: mean aggregation (one warp per node, monolithic) --------
__global__ void agg_kernel(const int* __restrict__ edges) {
    int node = (int)((blockIdx.x * blockDim.x + threadIdx.x) >> 5);
    int lane = threadIdx.x & 31;
    if (node >= GN) return;
    int is64 = g_is64;
    int e = -1;
    if (lane < MAXDEG) {
        if (is64) {
            long long t = ((const long long*)edges)[(size_t)node * MAXDEG + lane];
            e = (int)t;
        } else {
            e = edges[node * MAXDEG + lane];
        }
    }
    unsigned bal = __ballot_sync(0xffffffffu, e >= 0);
    float inv = 1.0f / (float)__popc(bal & 0xffffu);

    float acc[8];
#pragma unroll
    for (int q = 0; q < 8; q++) acc[q] = 0.0f;

#pragma unroll
    for (int q4 = 0; q4 < 4; q4++) {
        uint4 v[4];
#pragma unroll
        for (int d = 0; d < 4; d++) {
            int ej = __shfl_sync(0xffffffffu, e, q4 * 4 + d);
            unsigned row = (ej >= 0) ? (unsigned)ej : (unsigned)GN;   // pad -> zero row
            v[d] = *(const uint4*)(g_xh + (size_t)row * GD + lane * 8);
        }
        const __half2* p0 = (const __half2*)&v[0];
        const __half2* p1 = (const __half2*)&v[1];
        const __half2* p2 = (const __half2*)&v[2];
        const __half2* p3 = (const __half2*)&v[3];
#pragma unroll
        for (int j = 0; j < 4; j++) {
            __half2 s01 = __hadd2(p0[j], p1[j]);
            __half2 s23 = __hadd2(p2[j], p3[j]);
            __half2 s = __hadd2(s01, s23);
            float2 f = __half22float2(s);
            acc[j * 2] += f.x;
            acc[j * 2 + 1] += f.y;
        }
    }
    __half2 r0 = __floats2half2_rn(acc[0] * inv, acc[1] * inv);
    __half2 r1 = __floats2half2_rn(acc[2] * inv, acc[3] * inv);
    __half2 r2 = __floats2half2_rn(acc[4] * inv, acc[5] * inv);
    __half2 r3 = __floats2half2_rn(acc[6] * inv, acc[7] * inv);
    uint4 o;
    o.x = *reinterpret_cast<unsigned*>(&r0);
    o.y = *reinterpret_cast<unsigned*>(&r1);
    o.z = *reinterpret_cast<unsigned*>(&r2);
    o.w = *reinterpret_cast<unsigned*>(&r3);
    *(uint4*)(g_aggh + (size_t)node * GD + lane * 8) = o;
}

// ---------------- kernel 3: mma.sync GEMM, low-ldsm-traffic blocking ------------------
// out[M,256] = h[M,512] @ W^T + b.  CTA tile 128(M) x 128(N), 256 thr (8 warps),
// 2 CTAs/SM (64KB smem).  Warp grid 4(M) x 2(N), warp tile 32x64 (acc=64 regs).
// ldsm traffic: dupA=2, dupB=4 -> 6 B/output/chunk (25% less than the 64x128 tiling).
// Grid = 782 m-tiles x 2 n-halves.

#define KC 64
#define NCH 8

// SMEM: A dbuf 2 x 16KB @ 0 ; B dbuf 2 x 16KB @ 32768. 16B-seg XOR swizzle. Total 64KB.
#define SA(buf) ((buf) * 16384)
#define SB(buf) (32768 + (buf) * 16384)
#define SMEM_DYN 65536

__global__ void __launch_bounds__(256, 2)
gemm_kernel(const float* __restrict__ bias, float* __restrict__ out) {
    extern __shared__ char smem_raw[];
    uint32_t sb = smem_u32(smem_raw);
    const int tid = threadIdx.x;
    const int wid = tid >> 5, lane = tid & 31;
    const int wm = wid & 3;              // 0..3 -> 32 rows
    const int wn = wid >> 2;             // 0..1 -> 64 cols
    const int m0 = (blockIdx.x >> 1) * TILE_M;
    const int n0 = (blockIdx.x & 1) << 7;     // 0 or 128

    // ---- cp.async issue: A = 1024 16B segs (4/thr), B = 1024 segs (4/thr) ----
    auto issue_chunk = [&](int c, int buf) {
        const __half* asrc = (c < 4) ? g_xh : g_aggh;
        int kc0 = (c & 3) * KC;
#pragma unroll
        for (int i = 0; i < 4; i++) {
            int s = tid + i * 256;
            int row = s >> 3, seg = s & 7;
            int m = m0 + row;
            uint32_t dst = sb + SA(buf) + row * 128 + ((seg ^ (row & 7)) << 4);
            cp_async16(dst, asrc + (size_t)m * GD + kc0 + seg * 8, m < GN);
        }
#pragma unroll
        for (int i = 0; i < 4; i++) {
            int s = tid + i * 256;
            int n = s >> 3, seg = s & 7;
            uint32_t dst = sb + SB(buf) + n * 128 + ((seg ^ (n & 7)) << 4);
            cp_async16(dst, g_wh + (size_t)(n0 + n) * GK + c * KC + seg * 8, 1);
        }
        cp_async_commit();
    };

    float acc[2][8][4];
#pragma unroll
    for (int mt = 0; mt < 2; mt++)
#pragma unroll
        for (int nt = 0; nt < 8; nt++)
#pragma unroll
            for (int q = 0; q < 4; q++) acc[mt][nt][q] = 0.0f;

    issue_chunk(0, 0);

    const int lrow = lane & 15;          // row within 16-row tile
    const int lcg = lane >> 4;           // 16B column group (0/1)

#pragma unroll 1
    for (int c = 0; c < NCH; c++) {
        cp_async_wait0();
        __syncthreads();
        if (c + 1 < NCH) issue_chunk(c + 1, (c + 1) & 1);

        uint32_t abase = sb + SA(c & 1);
        uint32_t bbase = sb + SB(c & 1);
#pragma unroll
        for (int ks = 0; ks < 4; ks++) {
            uint32_t a0[2], a1[2], a2[2], a3[2];
            uint32_t b0[4], b1[4], b2[4], b3[4];
#pragma unroll
            for (int mt = 0; mt < 2; mt++) {
                int row = wm * 32 + mt * 16 + lrow;
                uint32_t addr = abase + row * 128 + (((ks * 2 + lcg) ^ (row & 7)) << 4);
                ldsm_x4(a0[mt], a1[mt], a2[mt], a3[mt], addr);
            }
#pragma unroll
            for (int np = 0; np < 4; np++) {     // 4 n-tile pairs (16 n-rows each)
                int row = wn * 64 + np * 16 + lrow;
                uint32_t addr = bbase + row * 128 + (((ks * 2 + lcg) ^ (row & 7)) << 4);
                ldsm_x4(b0[np], b1[np], b2[np], b3[np], addr);
            }
#pragma unroll
            for (int mt = 0; mt < 2; mt++) {
#pragma unroll
                for (int np = 0; np < 4; np++) {
                    mma16816(acc[mt][np * 2][0], acc[mt][np * 2][1],
                             acc[mt][np * 2][2], acc[mt][np * 2][3],
                             a0[mt], a1[mt], a2[mt], a3[mt], b0[np], b2[np]);
                    mma16816(acc[mt][np * 2 + 1][0], acc[mt][np * 2 + 1][1],
                             acc[mt][np * 2 + 1][2], acc[mt][np * 2 + 1][3],
                             a0[mt], a1[mt], a2[mt], a3[mt], b1[np], b3[np]);
                }
            }
        }
        __syncthreads();
    }

    // ---- epilogue: bias + store (warp: rows wm*32..+32, cols n0+wn*64..+64) ----
    const int qm = lane >> 2;            // 0..7 row within 8
    const int qn = (lane & 3) * 2;       // col pair
    float2 bb[8];
#pragma unroll
    for (int nt = 0; nt < 8; nt++) {
        int ncol = n0 + wn * 64 + nt * 8 + qn;
        bb[nt] = *(const float2*)(bias + ncol);
    }
#pragma unroll
    for (int mt = 0; mt < 2; mt++) {
        int r0 = m0 + wm * 32 + mt * 16 + qm;
        int r1 = r0 + 8;
#pragma unroll
        for (int nt = 0; nt < 8; nt++) {
            int ncol = n0 + wn * 64 + nt * 8 + qn;
            if (r0 < GN) {
                float2 v = make_float2(acc[mt][nt][0] + bb[nt].x, acc[mt][nt][1] + bb[nt].y);
                *(float2*)(out + (size_t)r0 * GD + ncol) = v;
            }
            if (r1 < GN) {
                float2 v = make_float2(acc[mt][nt][2] + bb[nt].x, acc[mt][nt][3] + bb[nt].y);
                *(float2*)(out + (size_t)r1 * GD + ncol) = v;
            }
        }
    }
}

// ---------------- launch: R13 structure (sequential core, tiny prep forked) ----------
extern "C" void kernel_launch(void* const* d_in, const int* in_sizes, int n_in,
                              void* d_out, int out_size) {
    const float* x  = (const float*)d_in[0];
    const int*   ei = (const int*)d_in[1];
    const float* W  = (const float*)d_in[2];
    const float* b  = (const float*)d_in[3];
    float* out = (float*)d_out;
    (void)in_sizes; (void)n_in; (void)out_size;

    static int init_done = 0;
    static int overlap_ok = 1;
    static cudaStream_t s1;
    static cudaEvent_t e0, e1;
    if (!init_done) {
        init_done = 1;
        cudaFuncSetAttribute(gemm_kernel, cudaFuncAttributeMaxDynamicSharedMemorySize, SMEM_DYN);
        if (cudaStreamCreateWithFlags(&s1, cudaStreamNonBlocking) != cudaSuccess) overlap_ok = 0;
        if (cudaEventCreateWithFlags(&e0, cudaEventDisableTiming) != cudaSuccess) overlap_ok = 0;
        if (cudaEventCreateWithFlags(&e1, cudaEventDisableTiming) != cudaSuccess) overlap_ok = 0;
    }

    int cvt_threads = ((GN + 1) * GD) / 8;

    if (overlap_ok) {
        // Fork s1 from capture origin; tiny prep concurrent with big x cvt.
        cudaEventRecord(e0, 0);
        cudaStreamWaitEvent(s1, e0, 0);
        cvt_w_kernel<<<(GD * GK / 8 + 255) / 256, 256, 0, s1>>>(W);
        detect_kernel<<<1, 256, 0, s1>>>(ei);
        cudaEventRecord(e1, s1);
        cvt_x_kernel<<<(cvt_threads + 255) / 256, 256>>>(x);
        cudaStreamWaitEvent(0, e1, 0);    // join: agg needs g_is64; gemm needs g_wh
        agg_kernel<<<(GN + 7) / 8, 256>>>(ei);
        gemm_kernel<<<NCTAS_G, 256, SMEM_DYN>>>(b, out);
    } else {
        cvt_x_kernel<<<(cvt_threads + 255) / 256, 256>>>(x);
        cvt_w_kernel<<<(GD * GK / 8 + 255) / 256, 256>>>(W);
        detect_kernel<<<1, 256>>>(ei);
        agg_kernel<<<(GN + 7) / 8, 256>>>(ei);
        gemm_kernel<<<NCTAS_G, 256, SMEM_DYN>>>(b, out);
    }
}

// round 16
// speedup vs baseline: 1.2207x; 1.0151x over previous
#include <cuda_runtime.h>
#include <cuda_fp16.h>
#include <cuda_bf16.h>
#include <cstdint>

// ---------------- problem constants ----------------
#define GN 100000          // nodes
#define GD 256             // d_in = d_out
#define GK 512             // 2*d_in
#define MAXDEG 16

#define TILE_M 128
#define NMT ((GN + TILE_M - 1) / TILE_M)     // 782 m-tiles
#define NCTAS_G (NMT * 2)                    // x2 n-halves = 1564 CTAs

// ---------------- scratch (device globals; no allocs allowed) ----------------
__device__ __align__(256) __half g_xh[(GN + 1) * GD];   // x in fp16, + zero row at index GN
__device__ __align__(256) __half g_aggh[GN * GD];       // neighbor mean, fp16
__device__ __align__(256) __half g_wh[GK * GD];         // W in fp16, [n][k] row-major
__device__ int g_is64;                                  // edge_index dtype flag

// ---------------- small helpers ----------------
__device__ __forceinline__ uint32_t smem_u32(const void* p) {
    uint32_t a;
    asm("{ .reg .u64 t; cvta.to.shared.u64 t, %1; cvt.u32.u64 %0, t; }" : "=r"(a) : "l"(p));
    return a;
}

__device__ __forceinline__ void cp_async16(uint32_t dst, const void* src, int pred) {
    int sz = pred ? 16 : 0;
    asm volatile("cp.async.cg.shared.global [%0], [%1], 16, %2;"
                 :: "r"(dst), "l"(src), "r"(sz) : "memory");
}
__device__ __forceinline__ void cp_async_commit() {
    asm volatile("cp.async.commit_group;" ::: "memory");
}
__device__ __forceinline__ void cp_async_wait0() {
    asm volatile("cp.async.wait_group 0;" ::: "memory");
}

__device__ __forceinline__ void ldsm_x4(uint32_t& r0, uint32_t& r1, uint32_t& r2, uint32_t& r3,
                                        uint32_t addr) {
    asm volatile("ldmatrix.sync.aligned.m8n8.x4.shared.b16 {%0,%1,%2,%3}, [%4];"
                 : "=r"(r0), "=r"(r1), "=r"(r2), "=r"(r3) : "r"(addr));
}

__device__ __forceinline__ void mma16816(float& c0, float& c1, float& c2, float& c3,
                                         uint32_t a0, uint32_t a1, uint32_t a2, uint32_t a3,
                                         uint32_t b0, uint32_t b1) {
    asm volatile(
        "mma.sync.aligned.m16n8k16.row.col.f32.f16.f16.f32 "
        "{%0,%1,%2,%3}, {%4,%5,%6,%7}, {%8,%9}, {%0,%1,%2,%3};"
        : "+f"(c0), "+f"(c1), "+f"(c2), "+f"(c3)
        : "r"(a0), "r"(a1), "r"(a2), "r"(a3), "r"(b0), "r"(b1));
}

// evict-first global stores (single-use streams; keep L2 free for resident sets)
__device__ __forceinline__ void stcs_f2(float* p, float2 v) {
    asm volatile("st.global.cs.v2.f32 [%0], {%1,%2};"
                 :: "l"(p), "f"(v.x), "f"(v.y) : "memory");
}
__device__ __forceinline__ void stcs_u4(void* p, uint4 v) {
    asm volatile("st.global.cs.v4.b32 [%0], {%1,%2,%3,%4};"
                 :: "l"(p), "r"(v.x), "r"(v.y), "r"(v.z), "r"(v.w) : "memory");
}
__device__ __forceinline__ float4 ldcs_f4(const float* p) {
    float4 v;
    asm volatile("ld.global.cs.v4.f32 {%0,%1,%2,%3}, [%4];"
                 : "=f"(v.x), "=f"(v.y), "=f"(v.z), "=f"(v.w) : "l"(p));
    return v;
}

// ---------------- kernel 1: x -> fp16 (+ zero pad row); x read evict-first ----------
__global__ void cvt_x_kernel(const float* __restrict__ x) {
    size_t i = ((size_t)blockIdx.x * blockDim.x + threadIdx.x) * 8;
    const size_t total = (size_t)(GN + 1) * GD;
    if (i >= total) return;
    uint4 o;
    if (i < (size_t)GN * GD) {
        float4 a = ldcs_f4(x + i);
        float4 b = ldcs_f4(x + i + 4);
        __half2 h0 = __floats2half2_rn(a.x, a.y);
        __half2 h1 = __floats2half2_rn(a.z, a.w);
        __half2 h2 = __floats2half2_rn(b.x, b.y);
        __half2 h3 = __floats2half2_rn(b.z, b.w);
        o.x = *reinterpret_cast<unsigned*>(&h0);
        o.y = *reinterpret_cast<unsigned*>(&h1);
        o.z = *reinterpret_cast<unsigned*>(&h2);
        o.w = *reinterpret_cast<unsigned*>(&h3);
    } else {
        o = make_uint4(0, 0, 0, 0);
    }
    *(uint4*)(g_xh + i) = o;        // default policy: this IS the hot set for agg
}

// ---------------- kernel 1w: W -> fp16, + dtype detect in the extra block ------------
__global__ void cvt_w_detect_kernel(const float* __restrict__ W, const int* __restrict__ e) {
    if (blockIdx.x == 64) {                   // dtype detection block
        int v = e[2 * threadIdx.x + 1];       // odd 32-bit words of first rows
        int bad = (v != 0 && v != -1) ? 1 : 0;  // int64 => these are all 0 / -1
        int any = __syncthreads_or(bad);
        if (threadIdx.x == 0) g_is64 = any ? 0 : 1;
        return;
    }
    size_t i = ((size_t)blockIdx.x * blockDim.x + threadIdx.x) * 8;
    float4 a = *(const float4*)(W + i);
    float4 b = *(const float4*)(W + i + 4);
    __half2 h0 = __floats2half2_rn(a.x, a.y);
    __half2 h1 = __floats2half2_rn(a.z, a.w);
    __half2 h2 = __floats2half2_rn(b.x, b.y);
    __half2 h3 = __floats2half2_rn(b.z, b.w);
    uint4 o;
    o.x = *reinterpret_cast<unsigned*>(&h0);
    o.y = *reinterpret_cast<unsigned*>(&h1);
    o.z = *reinterpret_cast<unsigned*>(&h2);
    o.w = *reinterpret_cast<unsigned*>(&h3);
    *(uint4*)(g_wh + i) = o;
}

// ---------------- kernel 2: mean aggregation (one warp per node, monolithic) --------
// Edge reads and agg writes are single-use -> .cs, keeping L2 for the x gather set.
__global__ void agg_kernel(const int* __restrict__ edges) {
    int node = (int)((blockIdx.x * blockDim.x + threadIdx.x) >> 5);
    int lane = threadIdx.x & 31;
    if (node >= GN) return;
    int is64 = g_is64;
    int e = -1;
    if (lane < MAXDEG) {
        if (is64) {
            long long t = __ldcs((const long long*)edges + (size_t)node * MAXDEG + lane);
            e = (int)t;
        } else {
            e = __ldcs(edges + (size_t)node * MAXDEG + lane);
        }
    }
    unsigned bal = __ballot_sync(0xffffffffu, e >= 0);
    float inv = 1.0f / (float)__popc(bal & 0xffffu);

    float acc[8];
#pragma unroll
    for (int q = 0; q < 8; q++) acc[q] = 0.0f;

#pragma unroll
    for (int q4 = 0; q4 < 4; q4++) {
        uint4 v[4];
#pragma unroll
        for (int d = 0; d < 4; d++) {
            int ej = __shfl_sync(0xffffffffu, e, q4 * 4 + d);
            unsigned row = (ej >= 0) ? (unsigned)ej : (unsigned)GN;   // pad -> zero row
            v[d] = *(const uint4*)(g_xh + (size_t)row * GD + lane * 8);
        }
        const __half2* p0 = (const __half2*)&v[0];
        const __half2* p1 = (const __half2*)&v[1];
        const __half2* p2 = (const __half2*)&v[2];
        const __half2* p3 = (const __half2*)&v[3];
#pragma unroll
        for (int j = 0; j < 4; j++) {
            __half2 s01 = __hadd2(p0[j], p1[j]);
            __half2 s23 = __hadd2(p2[j], p3[j]);
            __half2 s = __hadd2(s01, s23);
            float2 f = __half22float2(s);
            acc[j * 2] += f.x;
            acc[j * 2 + 1] += f.y;
        }
    }
    __half2 r0 = __floats2half2_rn(acc[0] * inv, acc[1] * inv);
    __half2 r1 = __floats2half2_rn(acc[2] * inv, acc[3] * inv);
    __half2 r2 = __floats2half2_rn(acc[4] * inv, acc[5] * inv);
    __half2 r3 = __floats2half2_rn(acc[6] * inv, acc[7] * inv);
    uint4 o;
    o.x = *reinterpret_cast<unsigned*>(&r0);
    o.y = *reinterpret_cast<unsigned*>(&r1);
    o.z = *reinterpret_cast<unsigned*>(&r2);
    o.w = *reinterpret_cast<unsigned*>(&r3);
    stcs_u4(g_aggh + (size_t)node * GD + lane * 8, o);
}

// ---------------- kernel 3: mma.sync GEMM, 128x128 CTA tile (R15-proven) -------------
// out[M,256] = h[M,512] @ W^T + b.  256 thr (8 warps), 2 CTAs/SM (64KB smem).
// Warp grid 4(M) x 2(N), warp tile 32x64 (acc=64 regs). Grid = 782 m-tiles x 2 n-halves.

#define KC 64
#define NCH 8

// SMEM: A dbuf 2 x 16KB @ 0 ; B dbuf 2 x 16KB @ 32768. 16B-seg XOR swizzle. Total 64KB.
#define SA(buf) ((buf) * 16384)
#define SB(buf) (32768 + (buf) * 16384)
#define SMEM_DYN 65536

__global__ void __launch_bounds__(256, 2)
gemm_kernel(const float* __restrict__ bias, float* __restrict__ out) {
    extern __shared__ char smem_raw[];
    uint32_t sb = smem_u32(smem_raw);
    const int tid = threadIdx.x;
    const int wid = tid >> 5, lane = tid & 31;
    const int wm = wid & 3;              // 0..3 -> 32 rows
    const int wn = wid >> 2;             // 0..1 -> 64 cols
    const int m0 = (blockIdx.x >> 1) * TILE_M;
    const int n0 = (blockIdx.x & 1) << 7;     // 0 or 128

    // ---- cp.async issue: A = 1024 16B segs (4/thr), B = 1024 segs (4/thr) ----
    auto issue_chunk = [&](int c, int buf) {
        const __half* asrc = (c < 4) ? g_xh : g_aggh;
        int kc0 = (c & 3) * KC;
#pragma unroll
        for (int i = 0; i < 4; i++) {
            int s = tid + i * 256;
            int row = s >> 3, seg = s & 7;
            int m = m0 + row;
            uint32_t dst = sb + SA(buf) + row * 128 + ((seg ^ (row & 7)) << 4);
            cp_async16(dst, asrc + (size_t)m * GD + kc0 + seg * 8, m < GN);
        }
#pragma unroll
        for (int i = 0; i < 4; i++) {
            int s = tid + i * 256;
            int n = s >> 3, seg = s & 7;
            uint32_t dst = sb + SB(buf) + n * 128 + ((seg ^ (n & 7)) << 4);
            cp_async16(dst, g_wh + (size_t)(n0 + n) * GK + c * KC + seg * 8, 1);
        }
        cp_async_commit();
    };

    float acc[2][8][4];
#pragma unroll
    for (int mt = 0; mt < 2; mt++)
#pragma unroll
        for (int nt = 0; nt < 8; nt++)
#pragma unroll
            for (int q = 0; q < 4; q++) acc[mt][nt][q] = 0.0f;

    issue_chunk(0, 0);

    const int lrow = lane & 15;          // row within 16-row tile
    const int lcg = lane >> 4;           // 16B column group (0/1)

#pragma unroll 1
    for (int c = 0; c < NCH; c++) {
        cp_async_wait0();
        __syncthreads();
        if (c + 1 < NCH) issue_chunk(c + 1, (c + 1) & 1);

        uint32_t abase = sb + SA(c & 1);
        uint32_t bbase = sb + SB(c & 1);
#pragma unroll
        for (int ks = 0; ks < 4; ks++) {
            uint32_t a0[2], a1[2], a2[2], a3[2];
            uint32_t b0[4], b1[4], b2[4], b3[4];
#pragma unroll
            for (int mt = 0; mt < 2; mt++) {
                int row = wm * 32 + mt * 16 + lrow;
                uint32_t addr = abase + row * 128 + (((ks * 2 + lcg) ^ (row & 7)) << 4);
                ldsm_x4(a0[mt], a1[mt], a2[mt], a3[mt], addr);
            }
#pragma unroll
            for (int np = 0; np < 4; np++) {     // 4 n-tile pairs (16 n-rows each)
                int row = wn * 64 + np * 16 + lrow;
                uint32_t addr = bbase + row * 128 + (((ks * 2 + lcg) ^ (row & 7)) << 4);
                ldsm_x4(b0[np], b1[np], b2[np], b3[np], addr);
            }
#pragma unroll
            for (int mt = 0; mt < 2; mt++) {
#pragma unroll
                for (int np = 0; np < 4; np++) {
                    mma16816(acc[mt][np * 2][0], acc[mt][np * 2][1],
                             acc[mt][np * 2][2], acc[mt][np * 2][3],
                             a0[mt], a1[mt], a2[mt], a3[mt], b0[np], b2[np]);
                    mma16816(acc[mt][np * 2 + 1][0], acc[mt][np * 2 + 1][1],
                             acc[mt][np * 2 + 1][2], acc[mt][np * 2 + 1][3],
                             a0[mt], a1[mt], a2[mt], a3[mt], b1[np], b3[np]);
                }
            }
        }
        __syncthreads();
    }

    // ---- epilogue: bias + evict-first store ----
    const int qm = lane >> 2;            // 0..7 row within 8
    const int qn = (lane & 3) * 2;       // col pair
    float2 bb[8];
#pragma unroll
    for (int nt = 0; nt < 8; nt++) {
        int ncol = n0 + wn * 64 + nt * 8 + qn;
        bb[nt] = *(const float2*)(bias + ncol);
    }
#pragma unroll
    for (int mt = 0; mt < 2; mt++) {
        int r0 = m0 + wm * 32 + mt * 16 + qm;
        int r1 = r0 + 8;
#pragma unroll
        for (int nt = 0; nt < 8; nt++) {
            int ncol = n0 + wn * 64 + nt * 8 + qn;
            if (r0 < GN) {
                stcs_f2(out + (size_t)r0 * GD + ncol,
                        make_float2(acc[mt][nt][0] + bb[nt].x, acc[mt][nt][1] + bb[nt].y));
            }
            if (r1 < GN) {
                stcs_f2(out + (size_t)r1 * GD + ncol,
                        make_float2(acc[mt][nt][2] + bb[nt].x, acc[mt][nt][3] + bb[nt].y));
            }
        }
    }
}

// ---------------- launch: sequential core, merged tiny prep forked -------------------
extern "C" void kernel_launch(void* const* d_in, const int* in_sizes, int n_in,
                              void* d_out, int out_size) {
    const float* x  = (const float*)d_in[0];
    const int*   ei = (const int*)d_in[1];
    const float* W  = (const float*)d_in[2];
    const float* b  = (const float*)d_in[3];
    float* out = (float*)d_out;
    (void)in_sizes; (void)n_in; (void)out_size;

    static int init_done = 0;
    static int overlap_ok = 1;
    static cudaStream_t s1;
    static cudaEvent_t e0, e1;
    if (!init_done) {
        init_done = 1;
        cudaFuncSetAttribute(gemm_kernel, cudaFuncAttributeMaxDynamicSharedMemorySize, SMEM_DYN);
        if (cudaStreamCreateWithFlags(&s1, cudaStreamNonBlocking) != cudaSuccess) overlap_ok = 0;
        if (cudaEventCreateWithFlags(&e0, cudaEventDisableTiming) != cudaSuccess) overlap_ok = 0;
        if (cudaEventCreateWithFlags(&e1, cudaEventDisableTiming) != cudaSuccess) overlap_ok = 0;
    }

    int cvt_threads = ((GN + 1) * GD) / 8;

    if (overlap_ok) {
        // Fork s1 from capture origin; merged W-cvt+detect concurrent with big x cvt.
        cudaEventRecord(e0, 0);
        cudaStreamWaitEvent(s1, e0, 0);
        cvt_w_detect_kernel<<<65, 256, 0, s1>>>(W, ei);
        cudaEventRecord(e1, s1);
        cvt_x_kernel<<<(cvt_threads + 255) / 256, 256>>>(x);
        cudaStreamWaitEvent(0, e1, 0);    // join: agg needs g_is64; gemm needs g_wh
        agg_kernel<<<(GN + 7) / 8, 256>>>(ei);
        gemm_kernel<<<NCTAS_G, 256, SMEM_DYN>>>(b, out);
    } else {
        cvt_x_kernel<<<(cvt_threads + 255) / 256, 256>>>(x);
        cvt_w_detect_kernel<<<65, 256>>>(W, ei);
        agg_kernel<<<(GN + 7) / 8, 256>>>(ei);
        gemm_kernel<<<NCTAS_G, 256, SMEM_DYN>>>(b, out);
    }
}

// round 17
// speedup vs baseline: 1.2269x; 1.0051x over previous
#include <cuda_runtime.h>
#include <cuda_fp16.h>
#include <cuda_bf16.h>
#include <cstdint>

// ---------------- problem constants ----------------
#define GN 100000          // nodes
#define GD 256             // d_in = d_out
#define GK 512             // 2*d_in
#define MAXDEG 16

#define TILE_M 128
#define NMT ((GN + TILE_M - 1) / TILE_M)     // 782 m-tiles
#define NCTAS_G (NMT * 4)                    // x4 n-quarters = 3128 CTAs

// ---------------- scratch (device globals; no allocs allowed) ----------------
__device__ __align__(256) __half g_xh[(GN + 1) * GD];   // x in fp16, + zero row at index GN
__device__ __align__(256) __half g_aggh[GN * GD];       // neighbor mean, fp16
__device__ __align__(256) __half g_wh[GK * GD];         // W in fp16, [n][k] row-major
__device__ int g_is64;                                  // edge_index dtype flag

// ---------------- small helpers ----------------
__device__ __forceinline__ uint32_t smem_u32(const void* p) {
    uint32_t a;
    asm("{ .reg .u64 t; cvta.to.shared.u64 t, %1; cvt.u32.u64 %0, t; }" : "=r"(a) : "l"(p));
    return a;
}

__device__ __forceinline__ void cp_async16(uint32_t dst, const void* src, int pred) {
    int sz = pred ? 16 : 0;
    asm volatile("cp.async.cg.shared.global [%0], [%1], 16, %2;"
                 :: "r"(dst), "l"(src), "r"(sz) : "memory");
}
__device__ __forceinline__ void cp_async_commit() {
    asm volatile("cp.async.commit_group;" ::: "memory");
}
__device__ __forceinline__ void cp_async_wait0() {
    asm volatile("cp.async.wait_group 0;" ::: "memory");
}

__device__ __forceinline__ void ldsm_x4(uint32_t& r0, uint32_t& r1, uint32_t& r2, uint32_t& r3,
                                        uint32_t addr) {
    asm volatile("ldmatrix.sync.aligned.m8n8.x4.shared.b16 {%0,%1,%2,%3}, [%4];"
                 : "=r"(r0), "=r"(r1), "=r"(r2), "=r"(r3) : "r"(addr));
}

__device__ __forceinline__ void mma16816(float& c0, float& c1, float& c2, float& c3,
                                         uint32_t a0, uint32_t a1, uint32_t a2, uint32_t a3,
                                         uint32_t b0, uint32_t b1) {
    asm volatile(
        "mma.sync.aligned.m16n8k16.row.col.f32.f16.f16.f32 "
        "{%0,%1,%2,%3}, {%4,%5,%6,%7}, {%8,%9}, {%0,%1,%2,%3};"
        : "+f"(c0), "+f"(c1), "+f"(c2), "+f"(c3)
        : "r"(a0), "r"(a1), "r"(a2), "r"(a3), "r"(b0), "r"(b1));
}

// evict-first global stores / loads (single-use streams)
__device__ __forceinline__ void stcs_f2(float* p, float2 v) {
    asm volatile("st.global.cs.v2.f32 [%0], {%1,%2};"
                 :: "l"(p), "f"(v.x), "f"(v.y) : "memory");
}
__device__ __forceinline__ void stcs_u4(void* p, uint4 v) {
    asm volatile("st.global.cs.v4.b32 [%0], {%1,%2,%3,%4};"
                 :: "l"(p), "r"(v.x), "r"(v.y), "r"(v.z), "r"(v.w) : "memory");
}
__device__ __forceinline__ float4 ldcs_f4(const float* p) {
    float4 v;
    asm volatile("ld.global.cs.v4.f32 {%0,%1,%2,%3}, [%4];"
                 : "=f"(v.x), "=f"(v.y), "=f"(v.z), "=f"(v.w) : "l"(p));
    return v;
}

// ---------------- kernel 1: x -> fp16 (+ zero pad row); x read evict-first ----------
__global__ void cvt_x_kernel(const float* __restrict__ x) {
    size_t i = ((size_t)blockIdx.x * blockDim.x + threadIdx.x) * 8;
    const size_t total = (size_t)(GN + 1) * GD;
    if (i >= total) return;
    uint4 o;
    if (i < (size_t)GN * GD) {
        float4 a = ldcs_f4(x + i);
        float4 b = ldcs_f4(x + i + 4);
        __half2 h0 = __floats2half2_rn(a.x, a.y);
        __half2 h1 = __floats2half2_rn(a.z, a.w);
        __half2 h2 = __floats2half2_rn(b.x, b.y);
        __half2 h3 = __floats2half2_rn(b.z, b.w);
        o.x = *reinterpret_cast<unsigned*>(&h0);
        o.y = *reinterpret_cast<unsigned*>(&h1);
        o.z = *reinterpret_cast<unsigned*>(&h2);
        o.w = *reinterpret_cast<unsigned*>(&h3);
    } else {
        o = make_uint4(0, 0, 0, 0);
    }
    *(uint4*)(g_xh + i) = o;        // default policy: this IS the hot set for agg
}

// ---------------- kernel 1w: W -> fp16, + dtype detect in the extra block ------------
__global__ void cvt_w_detect_kernel(const float* __restrict__ W, const int* __restrict__ e) {
    if (blockIdx.x == 64) {                   // dtype detection block
        int v = e[2 * threadIdx.x + 1];       // odd 32-bit words of first rows
        int bad = (v != 0 && v != -1) ? 1 : 0;  // int64 => these are all 0 / -1
        int any = __syncthreads_or(bad);
        if (threadIdx.x == 0) g_is64 = any ? 0 : 1;
        return;
    }
    size_t i = ((size_t)blockIdx.x * blockDim.x + threadIdx.x) * 8;
    float4 a = *(const float4*)(W + i);
    float4 b = *(const float4*)(W + i + 4);
    __half2 h0 = __floats2half2_rn(a.x, a.y);
    __half2 h1 = __floats2half2_rn(a.z, a.w);
    __half2 h2 = __floats2half2_rn(b.x, b.y);
    __half2 h3 = __floats2half2_rn(b.z, b.w);
    uint4 o;
    o.x = *reinterpret_cast<unsigned*>(&h0);
    o.y = *reinterpret_cast<unsigned*>(&h1);
    o.z = *reinterpret_cast<unsigned*>(&h2);
    o.w = *reinterpret_cast<unsigned*>(&h3);
    *(uint4*)(g_wh + i) = o;
}

// ---------------- kernel 2: mean aggregation (one warp per node, monolithic) --------
__global__ void agg_kernel(const int* __restrict__ edges) {
    int node = (int)((blockIdx.x * blockDim.x + threadIdx.x) >> 5);
    int lane = threadIdx.x & 31;
    if (node >= GN) return;
    int is64 = g_is64;
    int e = -1;
    if (lane < MAXDEG) {
        if (is64) {
            long long t = __ldcs((const long long*)edges + (size_t)node * MAXDEG + lane);
            e = (int)t;
        } else {
            e = __ldcs(edges + (size_t)node * MAXDEG + lane);
        }
    }
    unsigned bal = __ballot_sync(0xffffffffu, e >= 0);
    float inv = 1.0f / (float)__popc(bal & 0xffffu);

    float acc[8];
#pragma unroll
    for (int q = 0; q < 8; q++) acc[q] = 0.0f;

#pragma unroll
    for (int q4 = 0; q4 < 4; q4++) {
        uint4 v[4];
#pragma unroll
        for (int d = 0; d < 4; d++) {
            int ej = __shfl_sync(0xffffffffu, e, q4 * 4 + d);
            unsigned row = (ej >= 0) ? (unsigned)ej : (unsigned)GN;   // pad -> zero row
            v[d] = *(const uint4*)(g_xh + (size_t)row * GD + lane * 8);
        }
        const __half2* p0 = (const __half2*)&v[0];
        const __half2* p1 = (const __half2*)&v[1];
        const __half2* p2 = (const __half2*)&v[2];
        const __half2* p3 = (const __half2*)&v[3];
#pragma unroll
        for (int j = 0; j < 4; j++) {
            __half2 s01 = __hadd2(p0[j], p1[j]);
            __half2 s23 = __hadd2(p2[j], p3[j]);
            __half2 s = __hadd2(s01, s23);
            float2 f = __half22float2(s);
            acc[j * 2] += f.x;
            acc[j * 2 + 1] += f.y;
        }
    }
    __half2 r0 = __floats2half2_rn(acc[0] * inv, acc[1] * inv);
    __half2 r1 = __floats2half2_rn(acc[2] * inv, acc[3] * inv);
    __half2 r2 = __floats2half2_rn(acc[4] * inv, acc[5] * inv);
    __half2 r3 = __floats2half2_rn(acc[6] * inv, acc[7] * inv);
    uint4 o;
    o.x = *reinterpret_cast<unsigned*>(&r0);
    o.y = *reinterpret_cast<unsigned*>(&r1);
    o.z = *reinterpret_cast<unsigned*>(&r2);
    o.w = *reinterpret_cast<unsigned*>(&r3);
    stcs_u4(g_aggh + (size_t)node * GD + lane * 8, o);
}

// ---------------- kernel 3: mma.sync GEMM, fragment-pipelined, 3 CTAs/SM -------------
// out[M,256] = h[M,512] @ W^T + b.  CTA tile 128(M) x 64(N), 256 thr (8 warps),
// warp grid 4(M) x 2(N), warp tile 32x32 (acc=32 regs). Fragments double-buffered
// across ks (even/odd register sets) to kill the ldsm->mma WAR chain.
// Grid = 782 m-tiles x 4 n-quarters = 3128 CTAs = 7.04 waves at 3 CTAs/SM.

#define KC 64
#define NCH 8

// SMEM: A dbuf 2 x 16KB @ 0 ; B dbuf 2 x 8KB @ 32768. 16B-seg XOR swizzle. Total 48KB.
#define SA(buf) ((buf) * 16384)
#define SB(buf) (32768 + (buf) * 8192)
#define SMEM_DYN 49152

__global__ void __launch_bounds__(256, 3)
gemm_kernel(const float* __restrict__ bias, float* __restrict__ out) {
    extern __shared__ char smem_raw[];
    uint32_t sb = smem_u32(smem_raw);
    const int tid = threadIdx.x;
    const int wid = tid >> 5, lane = tid & 31;
    const int wm = wid & 3;              // 0..3 -> 32 rows
    const int wn = wid >> 2;             // 0..1 -> 32 cols
    const int m0 = (blockIdx.x >> 2) * TILE_M;
    const int n0 = (blockIdx.x & 3) << 6;     // 0/64/128/192

    // ---- cp.async issue: A = 1024 16B segs (4/thr), B = 512 segs (2/thr) ----
    auto issue_chunk = [&](int c, int buf) {
        const __half* asrc = (c < 4) ? g_xh : g_aggh;
        int kc0 = (c & 3) * KC;
#pragma unroll
        for (int i = 0; i < 4; i++) {
            int s = tid + i * 256;
            int row = s >> 3, seg = s & 7;
            int m = m0 + row;
            uint32_t dst = sb + SA(buf) + row * 128 + ((seg ^ (row & 7)) << 4);
            cp_async16(dst, asrc + (size_t)m * GD + kc0 + seg * 8, m < GN);
        }
#pragma unroll
        for (int i = 0; i < 2; i++) {
            int s = tid + i * 256;
            int n = s >> 3, seg = s & 7;
            uint32_t dst = sb + SB(buf) + n * 128 + ((seg ^ (n & 7)) << 4);
            cp_async16(dst, g_wh + (size_t)(n0 + n) * GK + c * KC + seg * 8, 1);
        }
        cp_async_commit();
    };

    float acc[2][4][4];
#pragma unroll
    for (int mt = 0; mt < 2; mt++)
#pragma unroll
        for (int nt = 0; nt < 4; nt++)
#pragma unroll
            for (int q = 0; q < 4; q++) acc[mt][nt][q] = 0.0f;

    issue_chunk(0, 0);

    const int lrow = lane & 15;          // row within 16-row tile
    const int lcg = lane >> 4;           // 16B column group (0/1)

    // double-buffered fragment sets: [set][mt*4 + r] / [set][np*4 + r]
    uint32_t aF[2][8], bF[2][8];

#pragma unroll 1
    for (int c = 0; c < NCH; c++) {
        cp_async_wait0();
        __syncthreads();
        if (c + 1 < NCH) issue_chunk(c + 1, (c + 1) & 1);

        uint32_t abase = sb + SA(c & 1);
        uint32_t bbase = sb + SB(c & 1);

        // load fragment set 0 (ks = 0)
#pragma unroll
        for (int mt = 0; mt < 2; mt++) {
            int row = wm * 32 + mt * 16 + lrow;
            uint32_t addr = abase + row * 128 + ((lcg ^ (row & 7)) << 4);
            ldsm_x4(aF[0][mt * 4], aF[0][mt * 4 + 1], aF[0][mt * 4 + 2], aF[0][mt * 4 + 3], addr);
        }
#pragma unroll
        for (int np = 0; np < 2; np++) {
            int row = wn * 32 + np * 16 + lrow;
            uint32_t addr = bbase + row * 128 + ((lcg ^ (row & 7)) << 4);
            ldsm_x4(bF[0][np * 4], bF[0][np * 4 + 1], bF[0][np * 4 + 2], bF[0][np * 4 + 3], addr);
        }

#pragma unroll
        for (int ks = 0; ks < 4; ks++) {
            const int cur = ks & 1;
            const int nxt = cur ^ 1;
            if (ks < 3) {
                // prefetch set for ks+1 into the other register set (no WAR on cur)
#pragma unroll
                for (int mt = 0; mt < 2; mt++) {
                    int row = wm * 32 + mt * 16 + lrow;
                    uint32_t addr = abase + row * 128 + ((((ks + 1) * 2 + lcg) ^ (row & 7)) << 4);
                    ldsm_x4(aF[nxt][mt * 4], aF[nxt][mt * 4 + 1],
                            aF[nxt][mt * 4 + 2], aF[nxt][mt * 4 + 3], addr);
                }
#pragma unroll
                for (int np = 0; np < 2; np++) {
                    int row = wn * 32 + np * 16 + lrow;
                    uint32_t addr = bbase + row * 128 + ((((ks + 1) * 2 + lcg) ^ (row & 7)) << 4);
                    ldsm_x4(bF[nxt][np * 4], bF[nxt][np * 4 + 1],
                            bF[nxt][np * 4 + 2], bF[nxt][np * 4 + 3], addr);
                }
            }
#pragma unroll
            for (int mt = 0; mt < 2; mt++) {
#pragma unroll
                for (int np = 0; np < 2; np++) {
                    mma16816(acc[mt][np * 2][0], acc[mt][np * 2][1],
                             acc[mt][np * 2][2], acc[mt][np * 2][3],
                             aF[cur][mt * 4], aF[cur][mt * 4 + 1],
                             aF[cur][mt * 4 + 2], aF[cur][mt * 4 + 3],
                             bF[cur][np * 4], bF[cur][np * 4 + 2]);
                    mma16816(acc[mt][np * 2 + 1][0], acc[mt][np * 2 + 1][1],
                             acc[mt][np * 2 + 1][2], acc[mt][np * 2 + 1][3],
                             aF[cur][mt * 4], aF[cur][mt * 4 + 1],
                             aF[cur][mt * 4 + 2], aF[cur][mt * 4 + 3],
                             bF[cur][np * 4 + 1], bF[cur][np * 4 + 3]);
                }
            }
        }
        __syncthreads();
    }

    // ---- epilogue: bias + evict-first store (warp: rows wm*32..+32, cols n0+wn*32..+32)
    const int qm = lane >> 2;            // 0..7 row within 8
    const int qn = (lane & 3) * 2;       // col pair
    float2 bb[4];
#pragma unroll
    for (int nt = 0; nt < 4; nt++) {
        int ncol = n0 + wn * 32 + nt * 8 + qn;
        bb[nt] = *(const float2*)(bias + ncol);
    }
#pragma unroll
    for (int mt = 0; mt < 2; mt++) {
        int r0 = m0 + wm * 32 + mt * 16 + qm;
        int r1 = r0 + 8;
#pragma unroll
        for (int nt = 0; nt < 4; nt++) {
            int ncol = n0 + wn * 32 + nt * 8 + qn;
            if (r0 < GN) {
                stcs_f2(out + (size_t)r0 * GD + ncol,
                        make_float2(acc[mt][nt][0] + bb[nt].x, acc[mt][nt][1] + bb[nt].y));
            }
            if (r1 < GN) {
                stcs_f2(out + (size_t)r1 * GD + ncol,
                        make_float2(acc[mt][nt][2] + bb[nt].x, acc[mt][nt][3] + bb[nt].y));
            }
        }
    }
}

// ---------------- launch: sequential core, merged tiny prep forked -------------------
extern "C" void kernel_launch(void* const* d_in, const int* in_sizes, int n_in,
                              void* d_out, int out_size) {
    const float* x  = (const float*)d_in[0];
    const int*   ei = (const int*)d_in[1];
    const float* W  = (const float*)d_in[2];
    const float* b  = (const float*)d_in[3];
    float* out = (float*)d_out;
    (void)in_sizes; (void)n_in; (void)out_size;

    static int init_done = 0;
    static int overlap_ok = 1;
    static cudaStream_t s1;
    static cudaEvent_t e0, e1;
    if (!init_done) {
        init_done = 1;
        cudaFuncSetAttribute(gemm_kernel, cudaFuncAttributeMaxDynamicSharedMemorySize, SMEM_DYN);
        if (cudaStreamCreateWithFlags(&s1, cudaStreamNonBlocking) != cudaSuccess) overlap_ok = 0;
        if (cudaEventCreateWithFlags(&e0, cudaEventDisableTiming) != cudaSuccess) overlap_ok = 0;
        if (cudaEventCreateWithFlags(&e1, cudaEventDisableTiming) != cudaSuccess) overlap_ok = 0;
    }

    int cvt_threads = ((GN + 1) * GD) / 8;

    if (overlap_ok) {
        // Fork s1 from capture origin; merged W-cvt+detect concurrent with big x cvt.
        cudaEventRecord(e0, 0);
        cudaStreamWaitEvent(s1, e0, 0);
        cvt_w_detect_kernel<<<65, 256, 0, s1>>>(W, ei);
        cudaEventRecord(e1, s1);
        cvt_x_kernel<<<(cvt_threads + 255) / 256, 256>>>(x);
        cudaStreamWaitEvent(0, e1, 0);    // join: agg needs g_is64; gemm needs g_wh
        agg_kernel<<<(GN + 7) / 8, 256>>>(ei);
        gemm_kernel<<<NCTAS_G, 256, SMEM_DYN>>>(b, out);
    } else {
        cvt_x_kernel<<<(cvt_threads + 255) / 256, 256>>>(x);
        cvt_w_detect_kernel<<<65, 256>>>(W, ei);
        agg_kernel<<<(GN + 7) / 8, 256>>>(ei);
        gemm_kernel<<<NCTAS_G, 256, SMEM_DYN>>>(b, out);
    }
}